// round 9
// baseline (speedup 1.0000x reference)
#include <cuda_runtime.h>
#include <cuda_fp16.h>
#include <math.h>
#include <stdint.h>

#define Bsz 4
#define Cc 64
#define CIc 32
#define Hh 96
#define Wd 96
#define Nn (Hh*Wd)          /* 9216 */
#define Mm ((Hh/2)*(Wd/2))  /* 2304 */
#define EPSv 1e-5f
#define TN 128
#define TM 64
#define NT (Nn/TN)          /* 72 */
#define JT (Mm/TM)          /* 36 */
#define LOG2E 1.4426950408889634f

/* ---------------- scratch (static device globals) ---------------- */
__device__ __half QfB[Bsz*Nn*Cc];   /* theta(x) * log2e */
__device__ __half KfB[Bsz*Mm*Cc];
__device__ __half VfB[Bsz*Mm*Cc];
__device__ float Zbuf[Bsz*CIc*Nn];
__device__ float g_sum[CIc];
__device__ float g_sumsq[CIc];

__device__ __forceinline__ uint32_t smem_u32(const void* p) {
    uint32_t a;
    asm("{ .reg .u64 t; cvta.to.shared.u64 t, %1; cvt.u32.u64 %0, t; }" : "=r"(a) : "l"(p));
    return a;
}
#define SWZ128(x) ((x) ^ (((x) >> 3) & 0x70))

#define LDM_X4(r0,r1,r2,r3,a) \
    asm volatile("ldmatrix.sync.aligned.m8n8.x4.shared.b16 {%0,%1,%2,%3}, [%4];" \
        : "=r"(r0),"=r"(r1),"=r"(r2),"=r"(r3) : "r"(a))
#define LDM_X4T(r0,r1,r2,r3,a) \
    asm volatile("ldmatrix.sync.aligned.m8n8.x4.trans.shared.b16 {%0,%1,%2,%3}, [%4];" \
        : "=r"(r0),"=r"(r1),"=r"(r2),"=r"(r3) : "r"(a))
/* f16-accumulator MMA: D/C are 2 packed f16x2 regs */
#define MMA16816H(d,a0,a1,a2,a3,b0,b1) \
    asm volatile("mma.sync.aligned.m16n8k16.row.col.f16.f16.f16.f16 " \
        "{%0,%1},{%2,%3,%4,%5},{%6,%7},{%0,%1};" \
        : "+r"((d)[0]),"+r"((d)[1]) \
        : "r"(a0),"r"(a1),"r"(a2),"r"(a3),"r"(b0),"r"(b1))
#define EX2H2(d, s) \
    asm volatile("ex2.approx.f16x2 %0, %1;" : "=r"(d) : "r"(s))
#define CP_A16(dst, src) \
    asm volatile("cp.async.cg.shared.global [%0], [%1], 16;" :: "r"(dst), "l"(src))
#define CP_COMMIT() asm volatile("cp.async.commit_group;" ::: "memory")
#define CP_WAIT(n)  asm volatile("cp.async.wait_group %0;" :: "n"(n) : "memory")

/* ---------------- SMEM layout (attn), bytes ---------------- */
#define SM_Q    0                    /* 128x64 fp16  16384 */
#define SM_ST   16384                /* 4 stages x {K 8192, V 8192} = 65536 */
#define STG_K(s) (SM_ST + (uint32_t)(s)*16384)
#define STG_V(s) (SM_ST + (uint32_t)(s)*16384 + 8192)
#define SM_W    81920                /* Wsm fp32 [c][32]  8192 */
#define SM_SRED 90112                /* 64 floats */
#define SM_TOT  90368
/* Zs (64 x 133 fp32 = 34048 B) overlaps SM_Q/stage region in the epilogue */

/* ================ Q = theta conv * log2e, fp16 (16 px/block) ================ */
__global__ void q_kernel(const float* __restrict__ x,
                         const float* __restrict__ theta_w,
                         const float* __restrict__ theta_b) {
    __shared__ float Tt[64][65];
    int tid = threadIdx.x;
    for (int i = tid; i < 64*64; i += 256) { int o = i >> 6, ci = i & 63; Tt[ci][o] = theta_w[i]; }
    if (blockIdx.x == 0 && tid < CIc) { g_sum[tid] = 0.f; g_sumsq[tid] = 0.f; }
    __syncthreads();
    int c = tid & 63, p = tid >> 6;
    float tb = theta_b[c];
#pragma unroll
    for (int q = 0; q < 4; q++) {
        int pix = blockIdx.x * 16 + p + q*4;
        int b = pix / Nn, n = pix % Nn;
        const float* xp = x + (size_t)b*Cc*Nn + n;
        float acc = 0.f;
#pragma unroll 8
        for (int ci = 0; ci < 64; ci++) acc += xp[(size_t)ci*Nn] * Tt[ci][c];
        QfB[((size_t)b*Nn + n)*Cc + c] = __float2half_rn((acc + tb) * LOG2E);
    }
}

/* ========== K = maxpool(phi(feature)), V = maxpool(g(x)), fp16, [b][m][c] ========== */
__global__ void kv_kernel(const float* __restrict__ x,
                          const float* __restrict__ feat,
                          const float* __restrict__ g_w, const float* __restrict__ g_b,
                          const float* __restrict__ phi_w, const float* __restrict__ phi_b) {
    __shared__ float Gt[64][65];
    __shared__ float Pw[32][65];
    int tid = threadIdx.x;
    for (int i = tid; i < 64*64; i += 256) { int o = i >> 6, ci = i & 63; Gt[ci][o] = g_w[i]; }
    for (int i = tid; i < 64*32; i += 256) { int o = i >> 5, ci = i & 31; Pw[ci][o] = phi_w[i]; }
    __syncthreads();
    int c = tid & 63, p = tid >> 6;
    float gb = g_b[c], pb = phi_b[c];
#pragma unroll
    for (int q = 0; q < 4; q++) {
        int gp = blockIdx.x * 16 + p + q*4;
        int b = gp / Mm, m = gp % Mm;
        int ph = m / (Wd/2), pw = m % (Wd/2);
        int n0 = (2*ph)*Wd + 2*pw;
        size_t idx = ((size_t)b*Mm + m)*Cc + c;

        const float* xb = x + (size_t)b*Cc*Nn;
        float a0=0.f,a1=0.f,a2=0.f,a3=0.f;
#pragma unroll 4
        for (int ci = 0; ci < 64; ci++) {
            float w = Gt[ci][c];
            const float* xr = xb + (size_t)ci*Nn + n0;
            a0 += xr[0]*w; a1 += xr[1]*w; a2 += xr[Wd]*w; a3 += xr[Wd+1]*w;
        }
        VfB[idx] = __float2half_rn(fmaxf(fmaxf(a0,a1), fmaxf(a2,a3)) + gb);

        const float* fb = feat + (size_t)b*CIc*Nn;
        float k0=0.f,k1=0.f,k2=0.f,k3=0.f;
#pragma unroll 4
        for (int ci = 0; ci < 32; ci++) {
            float w = Pw[ci][c];
            const float* fr = fb + (size_t)ci*Nn + n0;
            k0 += fr[0]*w; k1 += fr[1]*w; k2 += fr[Wd]*w; k3 += fr[Wd+1]*w;
        }
        KfB[idx] = __float2half_rn(fmaxf(fmaxf(k0,k1), fmaxf(k2,k3)) + pb);
    }
}

/* ================ fused HMMA attention (full fp16 inner pipe) + epilogue ================ */
__global__ void __launch_bounds__(256, 2)
attn_kernel(const float* __restrict__ x,
            const float* __restrict__ W_w, const float* __restrict__ W_b) {
    extern __shared__ char sm[];
    uint32_t smb = smem_u32(sm);
    int tid = threadIdx.x;
    int w = tid >> 5;
    int lane = tid & 31;
    int g = lane >> 2;
    int t = lane & 3;
    int b = blockIdx.x / NT;
    int n0 = (blockIdx.x % NT) * TN;

    const char* Kg = (const char*)(KfB + (size_t)b*Mm*Cc);
    const char* Vg = (const char*)(VfB + (size_t)b*Mm*Cc);

    /* per-thread staging coords */
    int s_row0 = tid >> 2;
    int s_ch0  = (tid & 3) * 2;
    uint32_t soff0 = SWZ128(s_row0*128 + s_ch0*16);
    uint32_t soff1 = SWZ128(s_row0*128 + (s_ch0+1)*16);
    size_t goff0 = (size_t)s_row0*128 + s_ch0*16;
    size_t goff1 = goff0 + 16;

#define PREFETCH_TILE(jj, st) do { \
        const char* kf = Kg + (size_t)(jj)*TM*Cc*2; \
        const char* vf = Vg + (size_t)(jj)*TM*Cc*2; \
        CP_A16(smb + STG_K(st) + soff0, kf + goff0); \
        CP_A16(smb + STG_K(st) + soff1, kf + goff1); \
        CP_A16(smb + STG_V(st) + soff0, vf + goff0); \
        CP_A16(smb + STG_V(st) + soff1, vf + goff1); \
        CP_COMMIT(); \
    } while (0)

    PREFETCH_TILE(0, 0);
    PREFETCH_TILE(1, 1);

    /* ---- load Q tile (128 rows x 128 B), swizzled ---- */
    {
        const uint4* qf = (const uint4*)(QfB + ((size_t)(b*Nn + n0))*Cc);
#pragma unroll
        for (int it = 0; it < 4; it++) {
            int idx = it*256 + tid;
            int row = idx >> 3, ch = idx & 7;
            *(uint4*)(sm + SM_Q + SWZ128(row*128 + ch*16)) = qf[idx];
        }
    }
    for (int i = tid; i < 2048; i += 256) {
        int o = i >> 6, c = i & 63;
        ((float*)(sm + SM_W))[c*32 + o] = W_w[i];
    }
    if (tid < 64) ((float*)(sm + SM_SRED))[tid] = 0.f;
    __syncthreads();

    uint32_t swz_mask = (uint32_t)(lane & 7) << 4;

    /* cache Q A-fragments (4 head-dim k-blocks) */
    uint32_t qh[4][4];
#pragma unroll
    for (int kb = 0; kb < 4; kb++) {
        uint32_t colb = (uint32_t)kb*32 + ((lane >> 4) << 4);
        uint32_t a = smb + SM_Q + (uint32_t)(16*w + (lane & 15))*128 + (colb ^ swz_mask);
        LDM_X4(qh[kb][0], qh[kb][1], qh[kb][2], qh[kb][3], a);
    }

    float O[8][4];
#pragma unroll
    for (int nb = 0; nb < 8; nb++)
#pragma unroll
        for (int r = 0; r < 4; r++) O[nb][r] = 0.f;
    float l0 = 0.f, l1 = 0.f;

    uint32_t k_row = (uint32_t)(lane & 7)*128 + (((uint32_t)lane >> 4) & 1)*1024;
    uint32_t k_half = (((uint32_t)lane >> 3) & 1) << 4;
    uint32_t v_row = (uint32_t)(lane & 15)*128;
    uint32_t v_nb  = (((uint32_t)lane >> 4) & 1) << 4;

    for (int j = 0; j < JT; j++) {
        if (j + 2 < JT) { PREFETCH_TILE(j + 2, (j + 2) & 3); CP_WAIT(2); }
        else if (j + 1 < JT) { CP_WAIT(1); }
        else { CP_WAIT(0); }
        __syncthreads();

        uint32_t KS = STG_K(j & 3), VS = STG_V(j & 3);

        /* per-tile f16 accumulators */
        uint32_t Oh[8][2];
#pragma unroll
        for (int nb = 0; nb < 8; nb++) { Oh[nb][0] = 0u; Oh[nb][1] = 0u; }
        __half2 lt0 = __float2half2_rn(0.f), lt1 = __float2half2_rn(0.f);

        /* ---- streaming over key blocks m2 (16 keys each): QK -> exp -> PV ---- */
#pragma unroll
        for (int m2 = 0; m2 < 4; m2++) {
            uint32_t S0[2] = {0u, 0u}, S1[2] = {0u, 0u};
#pragma unroll
            for (int kb = 0; kb < 4; kb++) {
                uint32_t b0, b1, b2, b3;
                uint32_t a = smb + KS + (uint32_t)m2*2048 + k_row
                    + ((((uint32_t)kb*32) + k_half) ^ swz_mask);
                LDM_X4(b0, b1, b2, b3, a);
                MMA16816H(S0, qh[kb][0], qh[kb][1], qh[kb][2], qh[kb][3], b0, b1);
                MMA16816H(S1, qh[kb][0], qh[kb][1], qh[kb][2], qh[kb][3], b2, b3);
            }

            /* p = exp2(S) directly in f16x2; these ARE the PV A-fragments */
            uint32_t pa[4];
            EX2H2(pa[0], S0[0]);   /* row g,   keys of first 8-block */
            EX2H2(pa[1], S0[1]);   /* row g+8, keys of first 8-block */
            EX2H2(pa[2], S1[0]);   /* row g,   keys of second 8-block */
            EX2H2(pa[3], S1[1]);   /* row g+8, keys of second 8-block */

            lt0 = __hadd2(lt0, *(__half2*)&pa[0]);
            lt0 = __hadd2(lt0, *(__half2*)&pa[2]);
            lt1 = __hadd2(lt1, *(__half2*)&pa[1]);
            lt1 = __hadd2(lt1, *(__half2*)&pa[3]);

#pragma unroll
            for (int nb2 = 0; nb2 < 4; nb2++) {
                uint32_t b0, b1, b2, b3;
                uint32_t a = smb + VS + (uint32_t)m2*2048 + v_row
                    + ((((uint32_t)nb2 << 5) + v_nb) ^ swz_mask);
                LDM_X4T(b0, b1, b2, b3, a);
                MMA16816H(Oh[2*nb2    ], pa[0], pa[1], pa[2], pa[3], b0, b1);
                MMA16816H(Oh[2*nb2 + 1], pa[0], pa[1], pa[2], pa[3], b2, b3);
            }
        }

        /* ---- per-tile flush f16 -> fp32 ---- */
#pragma unroll
        for (int nb = 0; nb < 8; nb++) {
            __half2 v0 = *(__half2*)&Oh[nb][0];
            __half2 v1 = *(__half2*)&Oh[nb][1];
            O[nb][0] += __low2float(v0);  O[nb][1] += __high2float(v0);
            O[nb][2] += __low2float(v1);  O[nb][3] += __high2float(v1);
        }
        l0 += __low2float(lt0) + __high2float(lt0);
        l1 += __low2float(lt1) + __high2float(lt1);
    }

    /* ---- reduce l across the 4-lane group ---- */
    l0 += __shfl_xor_sync(0xffffffffu, l0, 1);
    l0 += __shfl_xor_sync(0xffffffffu, l0, 2);
    l1 += __shfl_xor_sync(0xffffffffu, l1, 1);
    l1 += __shfl_xor_sync(0xffffffffu, l1, 2);

    /* ---- epilogue: z = O/l + x  ->  Zs smem (overlaps staging region) ---- */
    __syncthreads();
    float* Zs = (float*)sm;
    {
        const float* xb = x + (size_t)b*Cc*Nn + n0;
        int R0 = 16*w + g, R1 = R0 + 8;
        float inv0 = 1.f / l0, inv1 = 1.f / l1;
#pragma unroll
        for (int nb = 0; nb < 8; nb++) {
            int c0 = 8*nb + 2*t;
            Zs[(c0    )*133 + R0] = O[nb][0]*inv0 + xb[(size_t)(c0    )*Nn + R0];
            Zs[(c0 + 1)*133 + R0] = O[nb][1]*inv0 + xb[(size_t)(c0 + 1)*Nn + R0];
            Zs[(c0    )*133 + R1] = O[nb][2]*inv1 + xb[(size_t)(c0    )*Nn + R1];
            Zs[(c0 + 1)*133 + R1] = O[nb][3]*inv1 + xb[(size_t)(c0 + 1)*Nn + R1];
        }
    }
    __syncthreads();

    /* ---- W conv (64->32) + BN stats ---- */
    {
        int row = tid & 127, half = tid >> 7;
        int ob = half * 16;
        const float* Wsm = (const float*)(sm + SM_W);
        float acc[16];
#pragma unroll
        for (int oo = 0; oo < 16; oo++) acc[oo] = 0.f;
#pragma unroll 4
        for (int c = 0; c < 64; c++) {
            float zc = Zs[c*133 + row];
            const float* wr = Wsm + c*32 + ob;
#pragma unroll
            for (int oo = 0; oo < 16; oo++) acc[oo] += zc * wr[oo];
        }
        float* sred = (float*)(sm + SM_SRED);
#pragma unroll
        for (int oo = 0; oo < 16; oo++) {
            int o = ob + oo;
            float zv = acc[oo] + W_b[o];
            Zbuf[((size_t)b*CIc + o)*Nn + n0 + row] = zv;
            float s = zv, q = zv*zv;
#pragma unroll
            for (int d = 16; d; d >>= 1) {
                s += __shfl_xor_sync(0xffffffffu, s, d);
                q += __shfl_xor_sync(0xffffffffu, q, d);
            }
            if ((tid & 31) == 0) { atomicAdd(&sred[o], s); atomicAdd(&sred[32 + o], q); }
        }
    }
    __syncthreads();
    if (tid < CIc) {
        float* sred = (float*)(sm + SM_SRED);
        atomicAdd(&g_sum[tid],   sred[tid]);
        atomicAdd(&g_sumsq[tid], sred[32 + tid]);
    }
}

/* ---------------- finalize batchnorm (float4) ---------------- */
__global__ void bn_kernel(const float* __restrict__ gamma,
                          const float* __restrict__ beta,
                          float* __restrict__ out) {
    int i4 = blockIdx.x * 256 + threadIdx.x;
    if (i4 >= (Bsz*CIc*Nn)/4) return;
    int o = (i4 / (Nn/4)) & 31;
    const float cnt = (float)(Bsz*Nn);
    float mean = g_sum[o] / cnt;
    float var  = g_sumsq[o] / cnt - mean*mean;
    float sc = rsqrtf(var + EPSv) * gamma[o];
    float sh = beta[o] - mean*sc;
    float4 z = ((const float4*)Zbuf)[i4];
    float4 r;
    r.x = z.x*sc + sh; r.y = z.y*sc + sh; r.z = z.z*sc + sh; r.w = z.w*sc + sh;
    ((float4*)out)[i4] = r;
}

extern "C" void kernel_launch(void* const* d_in, const int* in_sizes, int n_in,
                              void* d_out, int out_size) {
    const float* x        = (const float*)d_in[0];
    const float* feature  = (const float*)d_in[1];
    const float* g_w      = (const float*)d_in[2];
    const float* g_b      = (const float*)d_in[3];
    const float* theta_w  = (const float*)d_in[4];
    const float* theta_b  = (const float*)d_in[5];
    const float* phi_w    = (const float*)d_in[6];
    const float* phi_b    = (const float*)d_in[7];
    const float* W_w      = (const float*)d_in[8];
    const float* W_b      = (const float*)d_in[9];
    const float* bn_gamma = (const float*)d_in[10];
    const float* bn_beta  = (const float*)d_in[11];
    float* out = (float*)d_out;

    cudaFuncSetAttribute(attn_kernel, cudaFuncAttributeMaxDynamicSharedMemorySize, SM_TOT);

    q_kernel<<<(Bsz*Nn)/16, 256>>>(x, theta_w, theta_b);
    kv_kernel<<<(Bsz*Mm)/16, 256>>>(x, feature, g_w, g_b, phi_w, phi_b);
    attn_kernel<<<Bsz*NT, 256, SM_TOT>>>(x, W_w, W_b);
    bn_kernel<<<((Bsz*CIc*Nn)/4 + 255)/256, 256>>>(bn_gamma, bn_beta, out);
}